// round 2
// baseline (speedup 1.0000x reference)
#include <cuda_runtime.h>
#include <cstdint>

#define Nn 50000
#define Ee 800000
#define C  128

// ---------------- device scratch (no allocs allowed) ----------------
__device__ float g_h[Nn * C];
__device__ float g_P[Nn * C];
__device__ float g_q[Nn * C];      // h @ (W_dst @ att_w1)
__device__ float g_k[Nn * C];      // h @ (W_src @ att_w1)
__device__ float g_v[Nn * C];
__device__ float g_Wq[C * C];
__device__ float g_Wk[C * C];
__device__ float g_delta[(size_t)Ee * C];   // 409.6 MB
__device__ float g_ea[(size_t)Ee * C];      // 409.6 MB
__device__ float g_z[Nn * C];
__device__ float g_agg[Nn * C];
__device__ int   g_is64;

// ---------------- edge-index dtype detection ----------------
__global__ void detect_kernel(const void* ei) {
    if (threadIdx.x == 0 && blockIdx.x == 0) {
        const long long* p = (const long long*)ei;
        int ok = 1;
        for (int i = 0; i < 256; i++) {
            long long v = p[i];
            if (v < 0 || v >= Nn) { ok = 0; break; }
        }
        g_is64 = ok;
    }
}

__device__ __forceinline__ int load_idx(const void* ei, long long flat) {
    if (g_is64) return (int)((const long long*)ei)[flat];
    return ((const int*)ei)[flat];
}

// ---------------- zero accumulators ----------------
__global__ void zero_kernel() {
    size_t total = (size_t)Nn * C;
    for (size_t i = (size_t)blockIdx.x * blockDim.x + threadIdx.x; i < total;
         i += (size_t)gridDim.x * blockDim.x) {
        g_z[i]   = 0.f;
        g_agg[i] = 0.f;
    }
}

// ---------------- weight folding: Wq = W_dst @ att_w1, Wk = W_src @ att_w1 ----------------
__global__ void fold_kernel(const float* __restrict__ Wd, const float* __restrict__ Ws,
                            const float* __restrict__ aw1) {
    const float* A = (blockIdx.y == 0) ? Wd : Ws;
    float*       O = (blockIdx.y == 0) ? g_Wq : g_Wk;
    int k = blockIdx.x;
    int c = threadIdx.x;
    __shared__ float arow[C];
    arow[c] = A[k * C + c];
    __syncthreads();
    float acc = 0.f;
#pragma unroll 8
    for (int j = 0; j < C; j++) acc += arow[j] * aw1[j * C + c];
    O[k * C + c] = acc;
}

// ---------------- shared 128x128x128 fp32 tile GEMM (512 threads) ----------------
// thread ty = tid/32 owns rows [ty*8, ty*8+8); tx = tid%32 owns cols [tx*4, tx*4+4)
__device__ __forceinline__ void gemm_tile(const float* __restrict__ sA,
                                          const float* __restrict__ sW,
                                          int ty, int tx, float acc[8][4]) {
#pragma unroll 2
    for (int k = 0; k < C; k += 4) {
        float4 w0 = *(const float4*)&sW[(k + 0) * C + tx * 4];
        float4 w1 = *(const float4*)&sW[(k + 1) * C + tx * 4];
        float4 w2 = *(const float4*)&sW[(k + 2) * C + tx * 4];
        float4 w3 = *(const float4*)&sW[(k + 3) * C + tx * 4];
#pragma unroll
        for (int i = 0; i < 8; i++) {
            float4 a = *(const float4*)&sA[(ty * 8 + i) * C + k];
            acc[i][0] += a.x * w0.x; acc[i][0] += a.y * w1.x; acc[i][0] += a.z * w2.x; acc[i][0] += a.w * w3.x;
            acc[i][1] += a.x * w0.y; acc[i][1] += a.y * w1.y; acc[i][1] += a.z * w2.y; acc[i][1] += a.w * w3.y;
            acc[i][2] += a.x * w0.z; acc[i][2] += a.y * w1.z; acc[i][2] += a.z * w2.z; acc[i][2] += a.w * w3.z;
            acc[i][3] += a.x * w0.w; acc[i][3] += a.y * w1.w; acc[i][3] += a.z * w2.w; acc[i][3] += a.w * w3.w;
        }
    }
}

// ---------------- node-level GEMM: out = act(X @ W + b), W 128x128 ----------------
__global__ __launch_bounds__(512) void node_gemm(const float* __restrict__ X,
                                                 const float* __restrict__ W,
                                                 const float* __restrict__ bias,
                                                 float* __restrict__ out,
                                                 int M, int do_relu) {
    extern __shared__ float sm[];
    float* sA = sm;           // [128][128]
    float* sW = sm + C * C;   // [128][128]
    int tid  = threadIdx.x;
    int row0 = blockIdx.x * 128;

    for (int i = tid * 4; i < C * C; i += 512 * 4)
        *(float4*)&sW[i] = *(const float4*)&W[i];
    for (int i = tid * 4; i < C * C; i += 512 * 4) {
        int r = i / C, c = i % C;
        float4 v = make_float4(0.f, 0.f, 0.f, 0.f);
        if (row0 + r < M) v = *(const float4*)&X[(size_t)(row0 + r) * C + c];
        *(float4*)&sA[i] = v;
    }
    __syncthreads();

    int ty = tid >> 5, tx = tid & 31;
    float acc[8][4];
#pragma unroll
    for (int i = 0; i < 8; i++)
#pragma unroll
        for (int j = 0; j < 4; j++) acc[i][j] = 0.f;

    gemm_tile(sA, sW, ty, tx, acc);

    float4 b = make_float4(0.f, 0.f, 0.f, 0.f);
    if (bias) b = *(const float4*)&bias[tx * 4];
#pragma unroll
    for (int i = 0; i < 8; i++) {
        int r = row0 + ty * 8 + i;
        if (r < M) {
            float4 o;
            o.x = acc[i][0] + b.x; o.y = acc[i][1] + b.y;
            o.z = acc[i][2] + b.z; o.w = acc[i][3] + b.w;
            if (do_relu) {
                o.x = fmaxf(o.x, 0.f); o.y = fmaxf(o.y, 0.f);
                o.z = fmaxf(o.z, 0.f); o.w = fmaxf(o.w, 0.f);
            }
            *(float4*)&out[(size_t)r * C + tx * 4] = o;
        }
    }
}

// ---------------- fused edge mega-kernel ----------------
// per 128-edge tile:
//   hp    = relu(P[dst]-P[src]+pos_b1)
//   delta = relu(hp @ pos_w2 + pos_b2)            -> g_delta
//   ha    = relu(delta @ att_w1 + q'[dst]-k'[src] + att_b1)
//   alpha = relu(ha @ att_w2 + att_b2)
//   ea    = exp(alpha)                            -> g_ea, atomicAdd g_z[dst]
__global__ __launch_bounds__(512) void edge_kernel(
    const void* __restrict__ ei,
    const float* __restrict__ pos_w2, const float* __restrict__ pos_b1,
    const float* __restrict__ pos_b2,
    const float* __restrict__ att_w1, const float* __restrict__ att_b1,
    const float* __restrict__ att_w2, const float* __restrict__ att_b2) {
    extern __shared__ float sm[];
    float* sA = sm;               // edge tile buf A [128][128]
    float* sB = sm + C * C;       // edge tile buf B [128][128]
    float* sW = sm + 2 * C * C;   // current weight  [128][128]
    __shared__ int s_src[128], s_dst[128];

    int tid = threadIdx.x;
    long long e0 = (long long)blockIdx.x * 128;
    if (tid < 128) {
        s_src[tid] = load_idx(ei, e0 + tid);
        s_dst[tid] = load_idx(ei, (long long)Ee + e0 + tid);
    }
    for (int i = tid * 4; i < C * C; i += 512 * 4)
        *(float4*)&sW[i] = *(const float4*)&pos_w2[i];
    __syncthreads();

    int ty = tid >> 5, tx = tid & 31;

    // stage 1: hp -> sA  (warp ty handles edges ty*8..+8, lane tx cols tx*4..+4)
    {
        float4 b1v = *(const float4*)&pos_b1[tx * 4];
#pragma unroll
        for (int i = 0; i < 8; i++) {
            int e = ty * 8 + i;
            int d = s_dst[e], s = s_src[e];
            float4 pd = *(const float4*)&g_P[(size_t)d * C + tx * 4];
            float4 ps = *(const float4*)&g_P[(size_t)s * C + tx * 4];
            float4 hp;
            hp.x = fmaxf(pd.x - ps.x + b1v.x, 0.f);
            hp.y = fmaxf(pd.y - ps.y + b1v.y, 0.f);
            hp.z = fmaxf(pd.z - ps.z + b1v.z, 0.f);
            hp.w = fmaxf(pd.w - ps.w + b1v.w, 0.f);
            *(float4*)&sA[e * C + tx * 4] = hp;
        }
    }
    __syncthreads();

    float acc[8][4];
#pragma unroll
    for (int i = 0; i < 8; i++)
#pragma unroll
        for (int j = 0; j < 4; j++) acc[i][j] = 0.f;

    // GEMM1: hp @ pos_w2
    gemm_tile(sA, sW, ty, tx, acc);
    __syncthreads();   // everyone done reading sW

    // reload weight = att_w1; delta epilogue -> sB + g_delta
    for (int i = tid * 4; i < C * C; i += 512 * 4)
        *(float4*)&sW[i] = *(const float4*)&att_w1[i];
    {
        float4 b2v = *(const float4*)&pos_b2[tx * 4];
#pragma unroll
        for (int i = 0; i < 8; i++) {
            int e = ty * 8 + i;
            float4 d4;
            d4.x = fmaxf(acc[i][0] + b2v.x, 0.f);
            d4.y = fmaxf(acc[i][1] + b2v.y, 0.f);
            d4.z = fmaxf(acc[i][2] + b2v.z, 0.f);
            d4.w = fmaxf(acc[i][3] + b2v.w, 0.f);
            *(float4*)&sB[e * C + tx * 4] = d4;
            *(float4*)&g_delta[((size_t)(e0 + e)) * C + tx * 4] = d4;
        }
    }
    __syncthreads();

#pragma unroll
    for (int i = 0; i < 8; i++)
#pragma unroll
        for (int j = 0; j < 4; j++) acc[i][j] = 0.f;

    // GEMM2: delta @ att_w1
    gemm_tile(sB, sW, ty, tx, acc);
    __syncthreads();   // done reading sW/sA

    // reload weight = att_w2; ha epilogue -> sA (with q'/k' gathers)
    for (int i = tid * 4; i < C * C; i += 512 * 4)
        *(float4*)&sW[i] = *(const float4*)&att_w2[i];
    {
        float4 ab1 = *(const float4*)&att_b1[tx * 4];
#pragma unroll
        for (int i = 0; i < 8; i++) {
            int e = ty * 8 + i;
            int d = s_dst[e], s = s_src[e];
            float4 q4 = *(const float4*)&g_q[(size_t)d * C + tx * 4];
            float4 k4 = *(const float4*)&g_k[(size_t)s * C + tx * 4];
            float4 h4;
            h4.x = fmaxf(acc[i][0] + q4.x - k4.x + ab1.x, 0.f);
            h4.y = fmaxf(acc[i][1] + q4.y - k4.y + ab1.y, 0.f);
            h4.z = fmaxf(acc[i][2] + q4.z - k4.z + ab1.z, 0.f);
            h4.w = fmaxf(acc[i][3] + q4.w - k4.w + ab1.w, 0.f);
            *(float4*)&sA[e * C + tx * 4] = h4;
        }
    }
    __syncthreads();

#pragma unroll
    for (int i = 0; i < 8; i++)
#pragma unroll
        for (int j = 0; j < 4; j++) acc[i][j] = 0.f;

    // GEMM3: ha @ att_w2
    gemm_tile(sA, sW, ty, tx, acc);

    // epilogue: ea = exp(relu(. + att_b2)); write g_ea; atomicAdd g_z[dst]
    {
        float4 ab2 = *(const float4*)&att_b2[tx * 4];
#pragma unroll
        for (int i = 0; i < 8; i++) {
            int e = ty * 8 + i;
            int d = s_dst[e];
            float4 ea4;
            ea4.x = expf(fmaxf(acc[i][0] + ab2.x, 0.f));
            ea4.y = expf(fmaxf(acc[i][1] + ab2.y, 0.f));
            ea4.z = expf(fmaxf(acc[i][2] + ab2.z, 0.f));
            ea4.w = expf(fmaxf(acc[i][3] + ab2.w, 0.f));
            *(float4*)&g_ea[((size_t)(e0 + e)) * C + tx * 4] = ea4;
            float* zp = &g_z[(size_t)d * C + tx * 4];
            atomicAdd(zp + 0, ea4.x);
            atomicAdd(zp + 1, ea4.y);
            atomicAdd(zp + 2, ea4.z);
            atomicAdd(zp + 3, ea4.w);
        }
    }
}

// ---------------- softmax-normalize + weighted aggregate ----------------
__global__ void finalize_kernel(const void* __restrict__ ei) {
    size_t idx = (size_t)blockIdx.x * blockDim.x + threadIdx.x;
    size_t e = idx >> 5;
    if (e >= (size_t)Ee) return;
    int cg = (int)(idx & 31) * 4;
    int s = load_idx(ei, (long long)e);
    int d = load_idx(ei, (long long)Ee + (long long)e);
    float4 ea4 = *(const float4*)&g_ea[e * C + cg];
    float4 z4  = *(const float4*)&g_z[(size_t)d * C + cg];
    float4 v4  = *(const float4*)&g_v[(size_t)s * C + cg];
    float4 dl  = *(const float4*)&g_delta[e * C + cg];
    float m0 = ea4.x / (z4.x + 1e-16f) * (v4.x + dl.x);
    float m1 = ea4.y / (z4.y + 1e-16f) * (v4.y + dl.y);
    float m2 = ea4.z / (z4.z + 1e-16f) * (v4.z + dl.z);
    float m3 = ea4.w / (z4.w + 1e-16f) * (v4.w + dl.w);
    float* ap = &g_agg[(size_t)d * C + cg];
    atomicAdd(ap + 0, m0);
    atomicAdd(ap + 1, m1);
    atomicAdd(ap + 2, m2);
    atomicAdd(ap + 3, m3);
}

// ---------------- launch ----------------
extern "C" void kernel_launch(void* const* d_in, const int* in_sizes, int n_in,
                              void* d_out, int out_size) {
    const float* x      = (const float*)d_in[0];
    const float* pos    = (const float*)d_in[1];
    const void*  ei     = d_in[2];
    const float* W_in   = (const float*)d_in[3];
    const float* b_in   = (const float*)d_in[4];
    const float* W_lin  = (const float*)d_in[5];
    const float* W_src  = (const float*)d_in[6];
    const float* W_dst  = (const float*)d_in[7];
    const float* pos_w1 = (const float*)d_in[8];
    const float* pos_b1 = (const float*)d_in[9];
    const float* pos_w2 = (const float*)d_in[10];
    const float* pos_b2 = (const float*)d_in[11];
    const float* att_w1 = (const float*)d_in[12];
    const float* att_b1 = (const float*)d_in[13];
    const float* att_w2 = (const float*)d_in[14];
    const float* att_b2 = (const float*)d_in[15];
    const float* W_out  = (const float*)d_in[16];
    const float* b_out  = (const float*)d_in[17];

    cudaFuncSetAttribute(node_gemm, cudaFuncAttributeMaxDynamicSharedMemorySize, 2 * C * C * 4);
    cudaFuncSetAttribute(edge_kernel, cudaFuncAttributeMaxDynamicSharedMemorySize, 3 * C * C * 4);

    float *p_h, *p_P, *p_q, *p_k, *p_v, *p_agg, *p_Wq, *p_Wk;
    cudaGetSymbolAddress((void**)&p_h, g_h);
    cudaGetSymbolAddress((void**)&p_P, g_P);
    cudaGetSymbolAddress((void**)&p_q, g_q);
    cudaGetSymbolAddress((void**)&p_k, g_k);
    cudaGetSymbolAddress((void**)&p_v, g_v);
    cudaGetSymbolAddress((void**)&p_agg, g_agg);
    cudaGetSymbolAddress((void**)&p_Wq, g_Wq);
    cudaGetSymbolAddress((void**)&p_Wk, g_Wk);

    const int node_blocks = (Nn + 127) / 128;   // 391
    const size_t ngemm_smem = 2 * C * C * 4;    // 128 KB
    const size_t edge_smem  = 3 * C * C * 4;    // 192 KB

    detect_kernel<<<1, 32>>>(ei);
    zero_kernel<<<4096, 512>>>();
    fold_kernel<<<dim3(C, 2), C>>>(W_dst, W_src, att_w1);

    node_gemm<<<node_blocks, 512, ngemm_smem>>>(x,   W_in,   b_in,    p_h, Nn, 1);
    node_gemm<<<node_blocks, 512, ngemm_smem>>>(pos, pos_w1, nullptr, p_P, Nn, 0);
    node_gemm<<<node_blocks, 512, ngemm_smem>>>(p_h, p_Wq,   nullptr, p_q, Nn, 0);
    node_gemm<<<node_blocks, 512, ngemm_smem>>>(p_h, p_Wk,   nullptr, p_k, Nn, 0);
    node_gemm<<<node_blocks, 512, ngemm_smem>>>(p_h, W_lin,  nullptr, p_v, Nn, 0);

    edge_kernel<<<Ee / 128, 512, edge_smem>>>(ei, pos_w2, pos_b1, pos_b2,
                                              att_w1, att_b1, att_w2, att_b2);

    finalize_kernel<<<(Ee * 32) / 256, 256>>>(ei);

    node_gemm<<<node_blocks, 512, ngemm_smem>>>(p_agg, W_out, b_out, (float*)d_out, Nn, 1);
}

// round 6
// speedup vs baseline: 2.8040x; 2.8040x over previous
#include <cuda_runtime.h>
#include <cstdint>

#define Nn 50000
#define Ee 800000
#define C  128
#define NTILES (Ee / 128)
#define AP 132              // padded A row stride (floats)

// ---------------- device scratch (no allocs allowed) ----------------
__device__ float g_h[Nn * C];
__device__ float g_P[Nn * C];
__device__ float g_q[Nn * C];
__device__ float g_k[Nn * C];
__device__ float g_v[Nn * C];
__device__ float g_Wq[C * C];
__device__ float g_Wk[C * C];
__device__ float g_wfrag[3][C * C];         // fragment-ordered tf32 weights (B^T)
__device__ float g_delta[(size_t)Ee * C];   // 409.6 MB
__device__ float g_ea[(size_t)Ee * C];      // 409.6 MB
__device__ float g_z[Nn * C];
__device__ float g_agg[Nn * C];
__device__ int   g_is64;

// ---------------- helpers ----------------
__device__ __forceinline__ float to_tf32(float f) {
    uint32_t t;
    asm("cvt.rna.tf32.f32 %0, %1;" : "=r"(t) : "f"(f));
    return __uint_as_float(t);
}

__device__ __forceinline__ void mma8(float* c, uint32_t a0, uint32_t a1, uint32_t a2,
                                     uint32_t a3, uint32_t b0, uint32_t b1) {
    asm volatile(
        "mma.sync.aligned.m16n8k8.row.col.f32.tf32.tf32.f32 "
        "{%0,%1,%2,%3}, {%4,%5,%6,%7}, {%8,%9}, {%0,%1,%2,%3};"
        : "+f"(c[0]), "+f"(c[1]), "+f"(c[2]), "+f"(c[3])
        : "r"(a0), "r"(a1), "r"(a2), "r"(a3), "r"(b0), "r"(b1));
}

// ---------------- edge-index dtype detection ----------------
__global__ void detect_kernel(const void* ei) {
    if (threadIdx.x == 0 && blockIdx.x == 0) {
        const long long* p = (const long long*)ei;
        int ok = 1;
        for (int i = 0; i < 256; i++) {
            long long v = p[i];
            if (v < 0 || v >= Nn) { ok = 0; break; }
        }
        g_is64 = ok;
    }
}
__device__ __forceinline__ int load_idx(const void* ei, long long flat) {
    if (g_is64) return (int)((const long long*)ei)[flat];
    return ((const int*)ei)[flat];
}

// ---------------- zero accumulators ----------------
__global__ void zero_kernel() {
    size_t total = (size_t)Nn * C;
    for (size_t i = (size_t)blockIdx.x * blockDim.x + threadIdx.x; i < total;
         i += (size_t)gridDim.x * blockDim.x) {
        g_z[i]   = 0.f;
        g_agg[i] = 0.f;
    }
}

// ---------------- weight folding: Wq = W_dst @ att_w1, Wk = W_src @ att_w1 ----------------
__global__ void fold_kernel(const float* __restrict__ Wd, const float* __restrict__ Ws,
                            const float* __restrict__ aw1) {
    const float* A = (blockIdx.y == 0) ? Wd : Ws;
    float*       O = (blockIdx.y == 0) ? g_Wq : g_Wk;
    int k = blockIdx.x;
    int c = threadIdx.x;
    __shared__ float arow[C];
    arow[c] = A[k * C + c];
    __syncthreads();
    float acc = 0.f;
#pragma unroll 8
    for (int j = 0; j < C; j++) acc += arow[j] * aw1[j * C + c];
    O[k * C + c] = acc;
}

// ---------------- fragment-ordered weight precompute ----------------
// B^T[n][k] = W[k][n]; fragment (nt, kt) holds 64 tf32 values in lane-major order:
//   idx = ((nt*16 + kt)*64 + lane*2 + j), value = W[kt*8 + (lane&3) + j*4][nt*8 + (lane>>2)]
__global__ void wfrag_kernel(const float* __restrict__ W0, const float* __restrict__ W1,
                             const float* __restrict__ W2) {
    const float* W = (blockIdx.y == 0) ? W0 : (blockIdx.y == 1) ? W1 : W2;
    int e = blockIdx.x * 256 + threadIdx.x;   // 0..16383
    int j    = e & 1;
    int lane = (e >> 1) & 31;
    int kt   = (e >> 6) & 15;
    int nt   = (e >> 10) & 15;
    int n = nt * 8 + (lane >> 2);
    int k = kt * 8 + (lane & 3) + j * 4;
    g_wfrag[blockIdx.y][e] = to_tf32(W[k * C + n]);
}

// ---------------- fp32 node GEMM (unchanged) ----------------
__device__ __forceinline__ void gemm_tile(const float* __restrict__ sA,
                                          const float* __restrict__ sW,
                                          int ty, int tx, float acc[8][4]) {
#pragma unroll 2
    for (int k = 0; k < C; k += 4) {
        float4 w0 = *(const float4*)&sW[(k + 0) * C + tx * 4];
        float4 w1 = *(const float4*)&sW[(k + 1) * C + tx * 4];
        float4 w2 = *(const float4*)&sW[(k + 2) * C + tx * 4];
        float4 w3 = *(const float4*)&sW[(k + 3) * C + tx * 4];
#pragma unroll
        for (int i = 0; i < 8; i++) {
            float4 a = *(const float4*)&sA[(ty * 8 + i) * C + k];
            acc[i][0] += a.x * w0.x; acc[i][0] += a.y * w1.x; acc[i][0] += a.z * w2.x; acc[i][0] += a.w * w3.x;
            acc[i][1] += a.x * w0.y; acc[i][1] += a.y * w1.y; acc[i][1] += a.z * w2.y; acc[i][1] += a.w * w3.y;
            acc[i][2] += a.x * w0.z; acc[i][2] += a.y * w1.z; acc[i][2] += a.z * w2.z; acc[i][2] += a.w * w3.z;
            acc[i][3] += a.x * w0.w; acc[i][3] += a.y * w1.w; acc[i][3] += a.z * w2.w; acc[i][3] += a.w * w3.w;
        }
    }
}

__global__ __launch_bounds__(512) void node_gemm(const float* __restrict__ X,
                                                 const float* __restrict__ W,
                                                 const float* __restrict__ bias,
                                                 float* __restrict__ out,
                                                 int M, int do_relu) {
    extern __shared__ float sm[];
    float* sA = sm;
    float* sW = sm + C * C;
    int tid  = threadIdx.x;
    int row0 = blockIdx.x * 128;

    for (int i = tid * 4; i < C * C; i += 512 * 4)
        *(float4*)&sW[i] = *(const float4*)&W[i];
    for (int i = tid * 4; i < C * C; i += 512 * 4) {
        int r = i / C, c = i % C;
        float4 v = make_float4(0.f, 0.f, 0.f, 0.f);
        if (row0 + r < M) v = *(const float4*)&X[(size_t)(row0 + r) * C + c];
        *(float4*)&sA[i] = v;
    }
    __syncthreads();

    int ty = tid >> 5, tx = tid & 31;
    float acc[8][4];
#pragma unroll
    for (int i = 0; i < 8; i++)
#pragma unroll
        for (int j = 0; j < 4; j++) acc[i][j] = 0.f;

    gemm_tile(sA, sW, ty, tx, acc);

    float4 b = make_float4(0.f, 0.f, 0.f, 0.f);
    if (bias) b = *(const float4*)&bias[tx * 4];
#pragma unroll
    for (int i = 0; i < 8; i++) {
        int r = row0 + ty * 8 + i;
        if (r < M) {
            float4 o;
            o.x = acc[i][0] + b.x; o.y = acc[i][1] + b.y;
            o.z = acc[i][2] + b.z; o.w = acc[i][3] + b.w;
            if (do_relu) {
                o.x = fmaxf(o.x, 0.f); o.y = fmaxf(o.y, 0.f);
                o.z = fmaxf(o.z, 0.f); o.w = fmaxf(o.w, 0.f);
            }
            *(float4*)&out[(size_t)r * C + tx * 4] = o;
        }
    }
}

// ---------------- tf32 mma.sync edge mega-kernel ----------------
// per 128-edge tile (persistent, grid = 296, 2 CTAs/SM):
//   sA = hp = relu(P[dst]-P[src]+pos_b1)        (tf32, padded rows)
//   MMA stage0: D = sA @ pos_w2^T -> delta -> sA, g_delta
//   MMA stage1: D = sA @ att_w1^T -> +q'[dst]-k'[src]+b, relu -> sA
//   MMA stage2: D = sA @ att_w2^T -> ea=exp(relu(.+b)) -> g_ea, atomic g_z[dst]
__global__ __launch_bounds__(256, 2) void edge_kernel_mma(
    const void* __restrict__ ei,
    const float* __restrict__ pos_b1, const float* __restrict__ pos_b2,
    const float* __restrict__ att_b1, const float* __restrict__ att_b2) {
    extern __shared__ float sA[];   // [128][AP]
    __shared__ int s_src[128], s_dst[128];
    __shared__ float s_pb1[C], s_pb2[C], s_ab1[C], s_ab2[C];

    int tid  = threadIdx.x;
    int wid  = tid >> 5, lane = tid & 31;
    int lr   = lane >> 2;       // row within fragment group (0..7)
    int lc   = lane & 3;        // k/col selector (0..3)

    if (tid < C) {
        s_pb1[tid] = pos_b1[tid];
        s_pb2[tid] = pos_b2[tid];
        s_ab1[tid] = att_b1[tid];
        s_ab2[tid] = att_b2[tid];
    }

    for (int t = blockIdx.x; t < NTILES; t += gridDim.x) {
        long long e0 = (long long)t * 128;
        __syncthreads();   // previous tile fully done (also covers bias init)
        if (tid < 128) {
            s_src[tid] = load_idx(ei, e0 + tid);
            s_dst[tid] = load_idx(ei, (long long)Ee + e0 + tid);
        }
        __syncthreads();

        // ---- build hp into sA (tf32), warp per edge row, lane per 4 cols ----
        {
            float4 b = *(const float4*)&s_pb1[lane * 4];
            for (int e = wid; e < 128; e += 8) {
                int d = s_dst[e], s = s_src[e];
                float4 pd = *(const float4*)&g_P[(size_t)d * C + lane * 4];
                float4 ps = *(const float4*)&g_P[(size_t)s * C + lane * 4];
                float4 hp;
                hp.x = to_tf32(fmaxf(pd.x - ps.x + b.x, 0.f));
                hp.y = to_tf32(fmaxf(pd.y - ps.y + b.y, 0.f));
                hp.z = to_tf32(fmaxf(pd.z - ps.z + b.z, 0.f));
                hp.w = to_tf32(fmaxf(pd.w - ps.w + b.w, 0.f));
                *(float4*)&sA[e * AP + lane * 4] = hp;
            }
        }
        __syncthreads();

#pragma unroll 1
        for (int s3 = 0; s3 < 3; s3++) {
            const float* WF = g_wfrag[s3];
            float acc[8][2][4];
#pragma unroll
            for (int mt = 0; mt < 8; mt++)
#pragma unroll
                for (int nt = 0; nt < 2; nt++)
#pragma unroll
                    for (int j = 0; j < 4; j++) acc[mt][nt][j] = 0.f;

            // ---- 256 MMAs: 16 k-steps x 8 m-tiles x 2 n-tiles ----
#pragma unroll 4
            for (int kt = 0; kt < 16; kt++) {
                float2 f0 = *(const float2*)&WF[(wid * 32 + kt) * 64 + lane * 2];
                float2 f1 = *(const float2*)&WF[(wid * 32 + 16 + kt) * 64 + lane * 2];
                uint32_t b00 = __float_as_uint(f0.x), b01 = __float_as_uint(f0.y);
                uint32_t b10 = __float_as_uint(f1.x), b11 = __float_as_uint(f1.y);
                const float* ap0 = &sA[lr * AP + kt * 8 + lc];
#pragma unroll
                for (int mt = 0; mt < 8; mt++) {
                    const float* ap = ap0 + mt * 16 * AP;
                    uint32_t a0 = __float_as_uint(ap[0]);
                    uint32_t a1 = __float_as_uint(ap[8 * AP]);
                    uint32_t a2 = __float_as_uint(ap[4]);
                    uint32_t a3 = __float_as_uint(ap[8 * AP + 4]);
                    mma8(acc[mt][0], a0, a1, a2, a3, b00, b01);
                    mma8(acc[mt][1], a0, a1, a2, a3, b10, b11);
                }
            }
            __syncthreads();   // all sA reads done before epilogue overwrites

            // ---- epilogue: thread owns rows {mt*16+lr, +8}, cols {wid*16+nt*8+2lc, +1} ----
            if (s3 == 0) {
#pragma unroll
                for (int mt = 0; mt < 8; mt++) {
                    int rlo = mt * 16 + lr;
#pragma unroll
                    for (int nt = 0; nt < 2; nt++) {
                        int col = wid * 16 + nt * 8 + lc * 2;
                        float b0 = s_pb2[col], b1 = s_pb2[col + 1];
                        float2 o;
                        o.x = fmaxf(acc[mt][nt][0] + b0, 0.f);
                        o.y = fmaxf(acc[mt][nt][1] + b1, 0.f);
                        *(float2*)&g_delta[((size_t)(e0 + rlo)) * C + col] = o;
                        sA[rlo * AP + col]     = to_tf32(o.x);
                        sA[rlo * AP + col + 1] = to_tf32(o.y);
                        o.x = fmaxf(acc[mt][nt][2] + b0, 0.f);
                        o.y = fmaxf(acc[mt][nt][3] + b1, 0.f);
                        *(float2*)&g_delta[((size_t)(e0 + rlo + 8)) * C + col] = o;
                        sA[(rlo + 8) * AP + col]     = to_tf32(o.x);
                        sA[(rlo + 8) * AP + col + 1] = to_tf32(o.y);
                    }
                }
            } else if (s3 == 1) {
#pragma unroll
                for (int mt = 0; mt < 8; mt++) {
                    int rlo = mt * 16 + lr;
                    int dlo = s_dst[rlo],     slo = s_src[rlo];
                    int dhi = s_dst[rlo + 8], shi = s_src[rlo + 8];
#pragma unroll
                    for (int nt = 0; nt < 2; nt++) {
                        int col = wid * 16 + nt * 8 + lc * 2;
                        float b0 = s_ab1[col], b1 = s_ab1[col + 1];
                        float2 q  = *(const float2*)&g_q[(size_t)dlo * C + col];
                        float2 kk = *(const float2*)&g_k[(size_t)slo * C + col];
                        sA[rlo * AP + col]     = to_tf32(fmaxf(acc[mt][nt][0] + q.x - kk.x + b0, 0.f));
                        sA[rlo * AP + col + 1] = to_tf32(fmaxf(acc[mt][nt][1] + q.y - kk.y + b1, 0.f));
                        q  = *(const float2*)&g_q[(size_t)dhi * C + col];
                        kk = *(const float2*)&g_k[(size_t)shi * C + col];
                        sA[(rlo + 8) * AP + col]     = to_tf32(fmaxf(acc[mt][nt][2] + q.x - kk.x + b0, 0.f));
                        sA[(rlo + 8) * AP + col + 1] = to_tf32(fmaxf(acc[mt][nt][3] + q.y - kk.y + b1, 0.f));
                    }
                }
            } else {
#pragma unroll
                for (int mt = 0; mt < 8; mt++) {
                    int rlo = mt * 16 + lr;
                    int dlo = s_dst[rlo], dhi = s_dst[rlo + 8];
#pragma unroll
                    for (int nt = 0; nt < 2; nt++) {
                        int col = wid * 16 + nt * 8 + lc * 2;
                        float b0 = s_ab2[col], b1 = s_ab2[col + 1];
                        float2 o;
                        o.x = expf(fmaxf(acc[mt][nt][0] + b0, 0.f));
                        o.y = expf(fmaxf(acc[mt][nt][1] + b1, 0.f));
                        *(float2*)&g_ea[((size_t)(e0 + rlo)) * C + col] = o;
                        atomicAdd(&g_z[(size_t)dlo * C + col],     o.x);
                        atomicAdd(&g_z[(size_t)dlo * C + col + 1], o.y);
                        o.x = expf(fmaxf(acc[mt][nt][2] + b0, 0.f));
                        o.y = expf(fmaxf(acc[mt][nt][3] + b1, 0.f));
                        *(float2*)&g_ea[((size_t)(e0 + rlo + 8)) * C + col] = o;
                        atomicAdd(&g_z[(size_t)dhi * C + col],     o.x);
                        atomicAdd(&g_z[(size_t)dhi * C + col + 1], o.y);
                    }
                }
            }
            __syncthreads();   // sA ready for next stage
        }
    }
}

// ---------------- softmax-normalize + weighted aggregate ----------------
__global__ void finalize_kernel(const void* __restrict__ ei) {
    size_t idx = (size_t)blockIdx.x * blockDim.x + threadIdx.x;
    size_t e = idx >> 5;
    if (e >= (size_t)Ee) return;
    int cg = (int)(idx & 31) * 4;
    int s = load_idx(ei, (long long)e);
    int d = load_idx(ei, (long long)Ee + (long long)e);
    float4 ea4 = *(const float4*)&g_ea[e * C + cg];
    float4 z4  = *(const float4*)&g_z[(size_t)d * C + cg];
    float4 v4  = *(const float4*)&g_v[(size_t)s * C + cg];
    float4 dl  = *(const float4*)&g_delta[e * C + cg];
    float m0 = ea4.x / (z4.x + 1e-16f) * (v4.x + dl.x);
    float m1 = ea4.y / (z4.y + 1e-16f) * (v4.y + dl.y);
    float m2 = ea4.z / (z4.z + 1e-16f) * (v4.z + dl.z);
    float m3 = ea4.w / (z4.w + 1e-16f) * (v4.w + dl.w);
    float* ap = &g_agg[(size_t)d * C + cg];
    atomicAdd(ap + 0, m0);
    atomicAdd(ap + 1, m1);
    atomicAdd(ap + 2, m2);
    atomicAdd(ap + 3, m3);
}

// ---------------- launch ----------------
extern "C" void kernel_launch(void* const* d_in, const int* in_sizes, int n_in,
                              void* d_out, int out_size) {
    const float* x      = (const float*)d_in[0];
    const float* pos    = (const float*)d_in[1];
    const void*  ei     = d_in[2];
    const float* W_in   = (const float*)d_in[3];
    const float* b_in   = (const float*)d_in[4];
    const float* W_lin  = (const float*)d_in[5];
    const float* W_src  = (const float*)d_in[6];
    const float* W_dst  = (const float*)d_in[7];
    const float* pos_w1 = (const float*)d_in[8];
    const float* pos_b1 = (const float*)d_in[9];
    const float* pos_w2 = (const float*)d_in[10];
    const float* pos_b2 = (const float*)d_in[11];
    const float* att_w1 = (const float*)d_in[12];
    const float* att_b1 = (const float*)d_in[13];
    const float* att_w2 = (const float*)d_in[14];
    const float* att_b2 = (const float*)d_in[15];
    const float* W_out  = (const float*)d_in[16];
    const float* b_out  = (const float*)d_in[17];

    cudaFuncSetAttribute(node_gemm, cudaFuncAttributeMaxDynamicSharedMemorySize, 2 * C * C * 4);
    cudaFuncSetAttribute(edge_kernel_mma, cudaFuncAttributeMaxDynamicSharedMemorySize,
                         128 * AP * 4);

    float *p_h, *p_P, *p_q, *p_k, *p_v, *p_agg, *p_Wq, *p_Wk;
    cudaGetSymbolAddress((void**)&p_h, g_h);
    cudaGetSymbolAddress((void**)&p_P, g_P);
    cudaGetSymbolAddress((void**)&p_q, g_q);
    cudaGetSymbolAddress((void**)&p_k, g_k);
    cudaGetSymbolAddress((void**)&p_v, g_v);
    cudaGetSymbolAddress((void**)&p_agg, g_agg);
    cudaGetSymbolAddress((void**)&p_Wq, g_Wq);
    cudaGetSymbolAddress((void**)&p_Wk, g_Wk);

    const int node_blocks = (Nn + 127) / 128;
    const size_t ngemm_smem = 2 * C * C * 4;
    const size_t edge_smem  = 128 * AP * 4;   // 67584 B

    detect_kernel<<<1, 32>>>(ei);
    zero_kernel<<<4096, 512>>>();
    fold_kernel<<<dim3(C, 2), C>>>(W_dst, W_src, att_w1);
    wfrag_kernel<<<dim3(64, 3), 256>>>(pos_w2, att_w1, att_w2);

    node_gemm<<<node_blocks, 512, ngemm_smem>>>(x,   W_in,   b_in,    p_h, Nn, 1);
    node_gemm<<<node_blocks, 512, ngemm_smem>>>(pos, pos_w1, nullptr, p_P, Nn, 0);
    node_gemm<<<node_blocks, 512, ngemm_smem>>>(p_h, p_Wq,   nullptr, p_q, Nn, 0);
    node_gemm<<<node_blocks, 512, ngemm_smem>>>(p_h, p_Wk,   nullptr, p_k, Nn, 0);
    node_gemm<<<node_blocks, 512, ngemm_smem>>>(p_h, W_lin,  nullptr, p_v, Nn, 0);

    edge_kernel_mma<<<296, 256, edge_smem>>>(ei, pos_b1, pos_b2, att_b1, att_b2);

    finalize_kernel<<<(Ee * 32) / 256, 256>>>(ei);

    node_gemm<<<node_blocks, 512, ngemm_smem>>>(p_agg, W_out, b_out, (float*)d_out, Nn, 1);
}

// round 8
// speedup vs baseline: 3.0984x; 1.1050x over previous
#include <cuda_runtime.h>
#include <cstdint>

#define Nn 50000
#define Ee 800000
#define C  128
#define NTILES (Ee / 128)
#define AP 132              // padded A row stride (floats)

// ---------------- device scratch (no allocs allowed) ----------------
__device__ float g_h[Nn * C];
__device__ float g_P[Nn * C];
__device__ float g_q[Nn * C];
__device__ float g_k[Nn * C];
__device__ float g_v[Nn * C];
__device__ float g_Wq[C * C];
__device__ float g_Wk[C * C];
__device__ float g_wfrag[9][C * C];         // fragment-ordered tf32 weights (B^T)
__device__ float g_delta[(size_t)Ee * C];   // 409.6 MB
__device__ float g_ea[(size_t)Ee * C];      // 409.6 MB
__device__ float g_z[Nn * C];
__device__ float g_agg[Nn * C];
__device__ int   g_is64;

// ---------------- helpers ----------------
__device__ __forceinline__ float to_tf32(float f) {
    uint32_t t;
    asm("cvt.rna.tf32.f32 %0, %1;" : "=r"(t) : "f"(f));
    return __uint_as_float(t);
}

__device__ __forceinline__ void mma8(float* c, uint32_t a0, uint32_t a1, uint32_t a2,
                                     uint32_t a3, uint32_t b0, uint32_t b1) {
    asm volatile(
        "mma.sync.aligned.m16n8k8.row.col.f32.tf32.tf32.f32 "
        "{%0,%1,%2,%3}, {%4,%5,%6,%7}, {%8,%9}, {%0,%1,%2,%3};"
        : "+f"(c[0]), "+f"(c[1]), "+f"(c[2]), "+f"(c[3])
        : "r"(a0), "r"(a1), "r"(a2), "r"(a3), "r"(b0), "r"(b1));
}

// ---------------- edge-index dtype detection ----------------
__global__ void detect_kernel(const void* ei) {
    if (threadIdx.x == 0 && blockIdx.x == 0) {
        const long long* p = (const long long*)ei;
        int ok = 1;
        for (int i = 0; i < 256; i++) {
            long long v = p[i];
            if (v < 0 || v >= Nn) { ok = 0; break; }
        }
        g_is64 = ok;
    }
}
__device__ __forceinline__ int load_idx(const void* ei, long long flat) {
    if (g_is64) return (int)((const long long*)ei)[flat];
    return ((const int*)ei)[flat];
}

// ---------------- zero accumulators ----------------
__global__ void zero_kernel() {
    size_t total = (size_t)Nn * C;
    for (size_t i = (size_t)blockIdx.x * blockDim.x + threadIdx.x; i < total;
         i += (size_t)gridDim.x * blockDim.x) {
        g_z[i]   = 0.f;
        g_agg[i] = 0.f;
    }
}

// ---------------- weight folding: Wq = W_dst @ att_w1, Wk = W_src @ att_w1 ----------------
__global__ void fold_kernel(const float* __restrict__ Wd, const float* __restrict__ Ws,
                            const float* __restrict__ aw1) {
    const float* A = (blockIdx.y == 0) ? Wd : Ws;
    float*       O = (blockIdx.y == 0) ? g_Wq : g_Wk;
    int k = blockIdx.x;
    int c = threadIdx.x;
    __shared__ float arow[C];
    arow[c] = A[k * C + c];
    __syncthreads();
    float acc = 0.f;
#pragma unroll 8
    for (int j = 0; j < C; j++) acc += arow[j] * aw1[j * C + c];
    O[k * C + c] = acc;
}

// ---------------- fragment-ordered weight precompute (9 slots) ----------------
// B^T[n][k] = W[k][n]; fragment (nt, kt) holds 64 tf32 values in lane-major order:
//   idx = ((nt*16 + kt)*64 + lane*2 + j), value = W[kt*8 + (lane&3) + j*4][nt*8 + (lane>>2)]
__global__ void wfrag_kernel9(const float* W0, const float* W1, const float* W2,
                              const float* W3, const float* W4, const float* W5,
                              const float* W6, const float* W7, const float* W8) {
    const float* Ws[9] = {W0, W1, W2, W3, W4, W5, W6, W7, W8};
    const float* W = Ws[blockIdx.y];
    int e = blockIdx.x * 256 + threadIdx.x;   // 0..16383
    int j    = e & 1;
    int lane = (e >> 1) & 31;
    int kt   = (e >> 6) & 15;
    int nt   = (e >> 10) & 15;
    int n = nt * 8 + (lane >> 2);
    int k = kt * 8 + (lane & 3) + j * 4;
    g_wfrag[blockIdx.y][e] = to_tf32(W[k * C + n]);
}

// ---------------- shared tf32 MMA core: 16 k-steps x 8 m-tiles x 2 n-tiles ----------------
__device__ __forceinline__ void mma_pass(const float* __restrict__ sA,
                                         const float* __restrict__ WF,
                                         int wid, int lr, int lc,
                                         float acc[8][2][4]) {
#pragma unroll
    for (int mt = 0; mt < 8; mt++)
#pragma unroll
        for (int nt = 0; nt < 2; nt++)
#pragma unroll
            for (int j = 0; j < 4; j++) acc[mt][nt][j] = 0.f;

    int lane = lr * 4 + lc;
#pragma unroll 4
    for (int kt = 0; kt < 16; kt++) {
        float2 f0 = *(const float2*)&WF[(wid * 32 + kt) * 64 + lane * 2];
        float2 f1 = *(const float2*)&WF[(wid * 32 + 16 + kt) * 64 + lane * 2];
        uint32_t b00 = __float_as_uint(f0.x), b01 = __float_as_uint(f0.y);
        uint32_t b10 = __float_as_uint(f1.x), b11 = __float_as_uint(f1.y);
        const float* ap0 = &sA[lr * AP + kt * 8 + lc];
#pragma unroll
        for (int mt = 0; mt < 8; mt++) {
            const float* ap = ap0 + mt * 16 * AP;
            uint32_t a0 = __float_as_uint(ap[0]);
            uint32_t a1 = __float_as_uint(ap[8 * AP]);
            uint32_t a2 = __float_as_uint(ap[4]);
            uint32_t a3 = __float_as_uint(ap[8 * AP + 4]);
            mma8(acc[mt][0], a0, a1, a2, a3, b00, b01);
            mma8(acc[mt][1], a0, a1, a2, a3, b10, b11);
        }
    }
}

// ---------------- tf32 node GEMM: out[w] = act(X @ W[w] + b), up to 3 weights ----------------
__global__ __launch_bounds__(256, 2) void node_mma(
    const float* __restrict__ X, int M,
    int w0, int w1, int w2, int nW,
    const float* __restrict__ bias, int do_relu,
    float* __restrict__ out0, float* __restrict__ out1, float* __restrict__ out2) {
    extern __shared__ float sA[];   // [128][AP]
    int tid  = threadIdx.x;
    int wid  = tid >> 5, lane = tid & 31;
    int lr   = lane >> 2, lc = lane & 3;
    int row0 = blockIdx.x * 128;

    // load A tile (tf32), zero-fill tail rows
    for (int i = tid * 4; i < C * C; i += 256 * 4) {
        int r = i >> 7, c = i & 127;
        float4 v = make_float4(0.f, 0.f, 0.f, 0.f);
        if (row0 + r < M) v = *(const float4*)&X[(size_t)(row0 + r) * C + c];
        v.x = to_tf32(v.x); v.y = to_tf32(v.y);
        v.z = to_tf32(v.z); v.w = to_tf32(v.w);
        *(float4*)&sA[r * AP + c] = v;
    }
    __syncthreads();

    int    ws[3]   = {w0, w1, w2};
    float* outs[3] = {out0, out1, out2};

#pragma unroll 1
    for (int wI = 0; wI < nW; wI++) {
        float acc[8][2][4];
        mma_pass(sA, g_wfrag[ws[wI]], wid, lr, lc, acc);

        float* out = outs[wI];
#pragma unroll
        for (int mt = 0; mt < 8; mt++) {
            int rlo = mt * 16 + lr;
#pragma unroll
            for (int nt = 0; nt < 2; nt++) {
                int col = wid * 16 + nt * 8 + lc * 2;
                float b0 = 0.f, b1 = 0.f;
                if (bias) { b0 = bias[col]; b1 = bias[col + 1]; }
                float2 o;
                o.x = acc[mt][nt][0] + b0;
                o.y = acc[mt][nt][1] + b1;
                if (do_relu) { o.x = fmaxf(o.x, 0.f); o.y = fmaxf(o.y, 0.f); }
                if (row0 + rlo < M)
                    *(float2*)&out[(size_t)(row0 + rlo) * C + col] = o;
                o.x = acc[mt][nt][2] + b0;
                o.y = acc[mt][nt][3] + b1;
                if (do_relu) { o.x = fmaxf(o.x, 0.f); o.y = fmaxf(o.y, 0.f); }
                if (row0 + rlo + 8 < M)
                    *(float2*)&out[(size_t)(row0 + rlo + 8) * C + col] = o;
            }
        }
    }
}

// ---------------- tf32 mma.sync edge mega-kernel ----------------
// per 128-edge tile (persistent, grid = 296, 2 CTAs/SM):
//   sA = hp = relu(P[dst]-P[src]+pos_b1)        (tf32, padded rows)
//   MMA stage0: D = sA @ pos_w2^T -> delta -> sA, g_delta
//   MMA stage1: D = sA @ att_w1^T -> +q'[dst]-k'[src]+b, relu -> sA
//   MMA stage2: D = sA @ att_w2^T -> ea=exp(relu(.+b)) -> g_ea, atomic g_z[dst]
__global__ __launch_bounds__(256, 2) void edge_kernel_mma(
    const void* __restrict__ ei,
    const float* __restrict__ pos_b1, const float* __restrict__ pos_b2,
    const float* __restrict__ att_b1, const float* __restrict__ att_b2) {
    extern __shared__ float sA[];   // [128][AP]
    __shared__ int s_src[128], s_dst[128];
    __shared__ float s_pb1[C], s_pb2[C], s_ab1[C], s_ab2[C];

    int tid  = threadIdx.x;
    int wid  = tid >> 5, lane = tid & 31;
    int lr   = lane >> 2;       // row within fragment group (0..7)
    int lc   = lane & 3;        // k/col selector (0..3)

    if (tid < C) {
        s_pb1[tid] = pos_b1[tid];
        s_pb2[tid] = pos_b2[tid];
        s_ab1[tid] = att_b1[tid];
        s_ab2[tid] = att_b2[tid];
    }

    for (int t = blockIdx.x; t < NTILES; t += gridDim.x) {
        long long e0 = (long long)t * 128;
        __syncthreads();   // previous tile fully done (also covers bias init)
        if (tid < 128) {
            s_src[tid] = load_idx(ei, e0 + tid);
            s_dst[tid] = load_idx(ei, (long long)Ee + e0 + tid);
        }
        __syncthreads();

        // ---- build hp into sA (tf32), warp per edge row, lane per 4 cols ----
        {
            float4 b = *(const float4*)&s_pb1[lane * 4];
            for (int e = wid; e < 128; e += 8) {
                int d = s_dst[e], s = s_src[e];
                float4 pd = *(const float4*)&g_P[(size_t)d * C + lane * 4];
                float4 ps = *(const float4*)&g_P[(size_t)s * C + lane * 4];
                float4 hp;
                hp.x = to_tf32(fmaxf(pd.x - ps.x + b.x, 0.f));
                hp.y = to_tf32(fmaxf(pd.y - ps.y + b.y, 0.f));
                hp.z = to_tf32(fmaxf(pd.z - ps.z + b.z, 0.f));
                hp.w = to_tf32(fmaxf(pd.w - ps.w + b.w, 0.f));
                *(float4*)&sA[e * AP + lane * 4] = hp;
            }
        }
        __syncthreads();

#pragma unroll 1
        for (int s3 = 0; s3 < 3; s3++) {
            float acc[8][2][4];
            mma_pass(sA, g_wfrag[s3], wid, lr, lc, acc);
            __syncthreads();   // all sA reads done before epilogue overwrites

            // ---- epilogue: thread owns rows {mt*16+lr, +8}, cols {wid*16+nt*8+2lc, +1} ----
            if (s3 == 0) {
#pragma unroll
                for (int mt = 0; mt < 8; mt++) {
                    int rlo = mt * 16 + lr;
#pragma unroll
                    for (int nt = 0; nt < 2; nt++) {
                        int col = wid * 16 + nt * 8 + lc * 2;
                        float b0 = s_pb2[col], b1 = s_pb2[col + 1];
                        float2 o;
                        o.x = fmaxf(acc[mt][nt][0] + b0, 0.f);
                        o.y = fmaxf(acc[mt][nt][1] + b1, 0.f);
                        *(float2*)&g_delta[((size_t)(e0 + rlo)) * C + col] = o;
                        sA[rlo * AP + col]     = to_tf32(o.x);
                        sA[rlo * AP + col + 1] = to_tf32(o.y);
                        o.x = fmaxf(acc[mt][nt][2] + b0, 0.f);
                        o.y = fmaxf(acc[mt][nt][3] + b1, 0.f);
                        *(float2*)&g_delta[((size_t)(e0 + rlo + 8)) * C + col] = o;
                        sA[(rlo + 8) * AP + col]     = to_tf32(o.x);
                        sA[(rlo + 8) * AP + col + 1] = to_tf32(o.y);
                    }
                }
            } else if (s3 == 1) {
#pragma unroll
                for (int mt = 0; mt < 8; mt++) {
                    int rlo = mt * 16 + lr;
                    int dlo = s_dst[rlo],     slo = s_src[rlo];
                    int dhi = s_dst[rlo + 8], shi = s_src[rlo + 8];
#pragma unroll
                    for (int nt = 0; nt < 2; nt++) {
                        int col = wid * 16 + nt * 8 + lc * 2;
                        float b0 = s_ab1[col], b1 = s_ab1[col + 1];
                        float2 q  = *(const float2*)&g_q[(size_t)dlo * C + col];
                        float2 kk = *(const float2*)&g_k[(size_t)slo * C + col];
                        sA[rlo * AP + col]     = to_tf32(fmaxf(acc[mt][nt][0] + q.x - kk.x + b0, 0.f));
                        sA[rlo * AP + col + 1] = to_tf32(fmaxf(acc[mt][nt][1] + q.y - kk.y + b1, 0.f));
                        q  = *(const float2*)&g_q[(size_t)dhi * C + col];
                        kk = *(const float2*)&g_k[(size_t)shi * C + col];
                        sA[(rlo + 8) * AP + col]     = to_tf32(fmaxf(acc[mt][nt][2] + q.x - kk.x + b0, 0.f));
                        sA[(rlo + 8) * AP + col + 1] = to_tf32(fmaxf(acc[mt][nt][3] + q.y - kk.y + b1, 0.f));
                    }
                }
            } else {
#pragma unroll
                for (int mt = 0; mt < 8; mt++) {
                    int rlo = mt * 16 + lr;
                    int dlo = s_dst[rlo], dhi = s_dst[rlo + 8];
#pragma unroll
                    for (int nt = 0; nt < 2; nt++) {
                        int col = wid * 16 + nt * 8 + lc * 2;
                        float b0 = s_ab2[col], b1 = s_ab2[col + 1];
                        float2 o;
                        o.x = expf(fmaxf(acc[mt][nt][0] + b0, 0.f));
                        o.y = expf(fmaxf(acc[mt][nt][1] + b1, 0.f));
                        *(float2*)&g_ea[((size_t)(e0 + rlo)) * C + col] = o;
                        atomicAdd(&g_z[(size_t)dlo * C + col],     o.x);
                        atomicAdd(&g_z[(size_t)dlo * C + col + 1], o.y);
                        o.x = expf(fmaxf(acc[mt][nt][2] + b0, 0.f));
                        o.y = expf(fmaxf(acc[mt][nt][3] + b1, 0.f));
                        *(float2*)&g_ea[((size_t)(e0 + rlo + 8)) * C + col] = o;
                        atomicAdd(&g_z[(size_t)dhi * C + col],     o.x);
                        atomicAdd(&g_z[(size_t)dhi * C + col + 1], o.y);
                    }
                }
            }
            __syncthreads();   // sA ready for next stage
        }
    }
}

// ---------------- softmax-normalize + weighted aggregate ----------------
__global__ void finalize_kernel(const void* __restrict__ ei) {
    size_t idx = (size_t)blockIdx.x * blockDim.x + threadIdx.x;
    size_t e = idx >> 5;
    if (e >= (size_t)Ee) return;
    int cg = (int)(idx & 31) * 4;
    int s = load_idx(ei, (long long)e);
    int d = load_idx(ei, (long long)Ee + (long long)e);
    float4 ea4 = *(const float4*)&g_ea[e * C + cg];
    float4 z4  = *(const float4*)&g_z[(size_t)d * C + cg];
    float4 v4  = *(const float4*)&g_v[(size_t)s * C + cg];
    float4 dl  = *(const float4*)&g_delta[e * C + cg];
    float m0 = ea4.x / (z4.x + 1e-16f) * (v4.x + dl.x);
    float m1 = ea4.y / (z4.y + 1e-16f) * (v4.y + dl.y);
    float m2 = ea4.z / (z4.z + 1e-16f) * (v4.z + dl.z);
    float m3 = ea4.w / (z4.w + 1e-16f) * (v4.w + dl.w);
    float* ap = &g_agg[(size_t)d * C + cg];
    atomicAdd(ap + 0, m0);
    atomicAdd(ap + 1, m1);
    atomicAdd(ap + 2, m2);
    atomicAdd(ap + 3, m3);
}

// ---------------- launch ----------------
extern "C" void kernel_launch(void* const* d_in, const int* in_sizes, int n_in,
                              void* d_out, int out_size) {
    const float* x      = (const float*)d_in[0];
    const float* pos    = (const float*)d_in[1];
    const void*  ei     = d_in[2];
    const float* W_in   = (const float*)d_in[3];
    const float* b_in   = (const float*)d_in[4];
    const float* W_lin  = (const float*)d_in[5];
    const float* W_src  = (const float*)d_in[6];
    const float* W_dst  = (const float*)d_in[7];
    const float* pos_w1 = (const float*)d_in[8];
    const float* pos_b1 = (const float*)d_in[9];
    const float* pos_w2 = (const float*)d_in[10];
    const float* pos_b2 = (const float*)d_in[11];
    const float* att_w1 = (const float*)d_in[12];
    const float* att_b1 = (const float*)d_in[13];
    const float* att_w2 = (const float*)d_in[14];
    const float* att_b2 = (const float*)d_in[15];
    const float* W_out  = (const float*)d_in[16];
    const float* b_out  = (const float*)d_in[17];

    const size_t mma_smem = 128 * AP * 4;   // 67584 B
    cudaFuncSetAttribute(edge_kernel_mma, cudaFuncAttributeMaxDynamicSharedMemorySize, mma_smem);
    cudaFuncSetAttribute(node_mma, cudaFuncAttributeMaxDynamicSharedMemorySize, mma_smem);

    float *p_h, *p_P, *p_q, *p_k, *p_v, *p_agg, *p_Wq, *p_Wk;
    cudaGetSymbolAddress((void**)&p_h, g_h);
    cudaGetSymbolAddress((void**)&p_P, g_P);
    cudaGetSymbolAddress((void**)&p_q, g_q);
    cudaGetSymbolAddress((void**)&p_k, g_k);
    cudaGetSymbolAddress((void**)&p_v, g_v);
    cudaGetSymbolAddress((void**)&p_agg, g_agg);
    cudaGetSymbolAddress((void**)&p_Wq, g_Wq);
    cudaGetSymbolAddress((void**)&p_Wk, g_Wk);

    const int node_blocks = (Nn + 127) / 128;   // 391

    detect_kernel<<<1, 32>>>(ei);
    zero_kernel<<<4096, 512>>>();
    fold_kernel<<<dim3(C, 2), C>>>(W_dst, W_src, att_w1);
    // slots: 0=pos_w2 1=att_w1 2=att_w2 3=W_in 4=pos_w1 5=Wq 6=Wk 7=W_lin 8=W_out
    wfrag_kernel9<<<dim3(64, 9), 256>>>(pos_w2, att_w1, att_w2, W_in, pos_w1,
                                        p_Wq, p_Wk, W_lin, W_out);

    // h = relu(x @ W_in + b_in)
    node_mma<<<node_blocks, 256, mma_smem>>>(x, Nn, 3, 0, 0, 1, b_in, 1,
                                             p_h, nullptr, nullptr);
    // P = pos @ pos_w1
    node_mma<<<node_blocks, 256, mma_smem>>>(pos, Nn, 4, 0, 0, 1, nullptr, 0,
                                             p_P, nullptr, nullptr);
    // q, k, v = h @ {Wq, Wk, W_lin}   (single pass over h)
    node_mma<<<node_blocks, 256, mma_smem>>>(p_h, Nn, 5, 6, 7, 3, nullptr, 0,
                                             p_q, p_k, p_v);

    edge_kernel_mma<<<296, 256, mma_smem>>>(ei, pos_b1, pos_b2, att_b1, att_b2);

    finalize_kernel<<<(Ee * 32) / 256, 256>>>(ei);

    // out = relu(agg @ W_out + b_out)
    node_mma<<<node_blocks, 256, mma_smem>>>(p_agg, Nn, 8, 0, 0, 1, b_out, 1,
                                             (float*)d_out, nullptr, nullptr);
}